// round 4
// baseline (speedup 1.0000x reference)
#include <cuda_runtime.h>
#include <cstdint>

#define BB 8
#define NN 8192
#define NG 512
#define GS 32
#define FPB 8   // fps CTAs per batch (64 CTAs total = single wave, co-resident)

// Scratch: transformed points (float4 for vectorized loads). 1 MB.
__device__ float4 g_x[BB * NN];
// Per-(batch, buffer, cta) tagged winner keys. Zeroed by xform_k every launch.
__device__ unsigned long long g_keys[BB][2][FPB];

// ---------------------------------------------------------------------------
// Kernel 1: SE3 transform.  x = R @ p + t.  Also zeroes g_keys for this launch.
// ---------------------------------------------------------------------------
__global__ void xform_k(const float* __restrict__ xyz,
                        const float* __restrict__ pose) {
    if (blockIdx.x == 0 && threadIdx.x < BB * 2 * FPB)
        ((unsigned long long*)g_keys)[threadIdx.x] = 0ull;

    int i = blockIdx.x * blockDim.x + threadIdx.x;
    if (i >= BB * NN) return;
    int b = i >> 13;
    const float* P = pose + b * 12;
    float x = xyz[3 * i + 0];
    float y = xyz[3 * i + 1];
    float z = xyz[3 * i + 2];
    float r0 = __fadd_rn(__fmaf_rn(__ldg(P + 2), z,
               __fmaf_rn(__ldg(P + 1), y, __fmul_rn(__ldg(P + 0), x))), __ldg(P + 3));
    float r1 = __fadd_rn(__fmaf_rn(__ldg(P + 6), z,
               __fmaf_rn(__ldg(P + 5), y, __fmul_rn(__ldg(P + 4), x))), __ldg(P + 7));
    float r2 = __fadd_rn(__fmaf_rn(__ldg(P + 10), z,
               __fmaf_rn(__ldg(P + 9), y, __fmul_rn(__ldg(P + 8), x))), __ldg(P + 11));
    g_x[i] = make_float4(r0, r1, r2, 0.0f);
}

// ---------------------------------------------------------------------------
// Kernel 2: FPS. 8 CTAs per batch (1 point/thread), coordinated through
// global-memory slots with embedded iteration tags (double-buffered).
//   warp argmax : redux.sync.max(dist bits) + redux.sync.min(tied idx)
//   CTA reduce  : 32 leader atomicMax on tagged key in smem
//   cross-CTA   : tid0 st.release its key to g_keys[b][buf][r];
//                 tid0 ld.acquire-polls all 8 slots for tag g+1, max locally;
//                 broadcasts winner via smem word; threads spin on tag.
// Key: (g+1)<<45 | dist_bits<<13 | (8191-idx)  -> max == (max dist, min idx)
// Lockstep safety: a CTA can only write buffer `buf` for iteration g+2 after
// every CTA has passed the spin for iteration g (which required reading all
// g-keys in `buf`), so slots are never overwritten while still being read.
// ---------------------------------------------------------------------------
__global__ __launch_bounds__(1024, 1) void fps_k(float* __restrict__ center_out) {
    const int tid = threadIdx.x;
    const int b = blockIdx.x >> 3;   // batch
    const int r = blockIdx.x & 7;    // cta-in-batch

    __shared__ unsigned long long s_lkey[2];
    __shared__ unsigned long long s_win[2];
    if (tid == 0) { s_lkey[0] = 0; s_lkey[1] = 0; s_win[0] = 0; s_win[1] = 0; }
    __syncthreads();

    const float4* __restrict__ xp = g_x + b * NN;
    const unsigned pidx = (unsigned)r * 1024u + (unsigned)tid;
    float4 p = __ldg(&xp[pidx]);
    float dst = 1e10f;

    if (r == 0 && tid == 0) {
        float4 c0 = __ldg(&xp[0]);
        center_out[(b * NG) * 3 + 0] = c0.x;
        center_out[(b * NG) * 3 + 1] = c0.y;
        center_out[(b * NG) * 3 + 2] = c0.z;
    }

    unsigned widx = 0;  // current center index (uniform across the 8 CTAs)

    for (int g = 0; g < NG - 1; g++) {
        const int buf = g & 1;
        const unsigned tagv = (unsigned)(g + 1);

        // --- distance update vs current center ---
        float4 c = __ldg(&xp[widx]);
        float dx = __fsub_rn(p.x, c.x);
        float dy = __fsub_rn(p.y, c.y);
        float dz = __fsub_rn(p.z, c.z);
        float d = __fadd_rn(__fadd_rn(__fmul_rn(dx, dx), __fmul_rn(dy, dy)),
                            __fmul_rn(dz, dz));
        dst = fminf(dst, d);

        // --- warp argmax via redux (uint order == float order for x >= 0) ---
        unsigned db = __float_as_uint(dst);
        unsigned wmax;
        asm volatile("redux.sync.max.u32 %0, %1, 0xffffffff;"
                     : "=r"(wmax) : "r"(db));
        unsigned cand = (db == wmax) ? pidx : 0xffffffffu;
        unsigned minidx;
        asm volatile("redux.sync.min.u32 %0, %1, 0xffffffff;"
                     : "=r"(minidx) : "r"(cand));

        // --- CTA reduce: 32 leaders atomicMax tagged key ---
        if ((tid & 31) == 0) {
            unsigned long long key = ((unsigned long long)tagv << 45) |
                                     ((unsigned long long)wmax << 13) |
                                     (8191u - minidx);
            atomicMax(&s_lkey[buf], key);
        }
        __syncthreads();

        // --- tid0: publish CTA key, poll all 8 slots, broadcast winner ---
        if (tid == 0) {
            unsigned long long k = s_lkey[buf];
            asm volatile("st.release.gpu.global.u64 [%0], %1;"
                         :: "l"(&g_keys[b][buf][r]), "l"(k) : "memory");
            unsigned long long m;
            bool done;
            do {
                m = 0ull;
                done = true;
#pragma unroll
                for (int j = 0; j < FPB; j++) {
                    unsigned long long v;
                    asm volatile("ld.acquire.gpu.global.u64 %0, [%1];"
                                 : "=l"(v) : "l"(&g_keys[b][buf][j]) : "memory");
                    if ((unsigned)(v >> 45) != tagv) done = false;
                    m = m > v ? m : v;
                }
            } while (!done);

            asm volatile("st.volatile.shared.u64 [%0], %1;"
                         :: "r"((unsigned)__cvta_generic_to_shared(&s_win[buf])),
                            "l"(m) : "memory");

            if (r == 0) {
                unsigned wi = 8191u - (unsigned)(m & 0x1fffu);
                float4 cw = __ldg(&xp[wi]);
                float* o = center_out + (b * NG + g + 1) * 3;
                o[0] = cw.x; o[1] = cw.y; o[2] = cw.z;
            }
        }

        // --- all threads: spin on local winner word (tag self-validates) ---
        unsigned long long w;
        const unsigned win_a = (unsigned)__cvta_generic_to_shared(&s_win[buf]);
        do {
            asm volatile("ld.volatile.shared.u64 %0, [%1];"
                         : "=l"(w) : "r"(win_a) : "memory");
        } while ((unsigned)(w >> 45) != tagv);
        widx = 8191u - (unsigned)(w & 0x1fffu);
    }
}

// ---------------------------------------------------------------------------
// Kernel 3: exact 32-NN per center (unchanged from passing R2 version).
// ---------------------------------------------------------------------------
__device__ __forceinline__ void ins4(unsigned long long k,
                                     unsigned long long& k0, unsigned long long& k1,
                                     unsigned long long& k2, unsigned long long& k3) {
    if (k < k3) {
        if (k < k2) {
            k3 = k2;
            if (k < k1) {
                k2 = k1;
                if (k < k0) { k1 = k0; k0 = k; } else { k1 = k; }
            } else { k2 = k; }
        } else { k3 = k; }
    }
}

__global__ __launch_bounds__(256) void knn_k(const float* __restrict__ center,
                                             float* __restrict__ neigh) {
    const int warp = threadIdx.x >> 5;
    const int lane = threadIdx.x & 31;
    const int c = blockIdx.x * 8 + warp;
    const int b = c >> 9;

    const float cx = __ldg(center + c * 3 + 0);
    const float cy = __ldg(center + c * 3 + 1);
    const float cz = __ldg(center + c * 3 + 2);
    const float4* xp = g_x + b * NN;

    const unsigned long long SENT = ~0ull;
    unsigned long long k0 = SENT, k1 = SENT, k2 = SENT, k3 = SENT;
    unsigned mask[8] = {0, 0, 0, 0, 0, 0, 0, 0};

    for (int i = 0; i < 256; i++) {
        int idx = i * 32 + lane;
        float4 p = __ldg(&xp[idx]);
        float dx = __fsub_rn(cx, p.x);
        float dy = __fsub_rn(cy, p.y);
        float dz = __fsub_rn(cz, p.z);
        float d = __fadd_rn(__fadd_rn(__fmul_rn(dx, dx), __fmul_rn(dy, dy)),
                            __fmul_rn(dz, dz));
        unsigned long long k =
            ((unsigned long long)__float_as_uint(d) << 32) | (unsigned)idx;
        ins4(k, k0, k1, k2, k3);
    }

    unsigned my_out_idx = 0;
    for (int r = 0; r < 32; r++) {
        unsigned long long h = k0;
        unsigned long long best = h;
#pragma unroll
        for (int o = 16; o > 0; o >>= 1) {
            unsigned long long v = __shfl_xor_sync(0xffffffffu, best, o);
            best = best < v ? best : v;
        }
        if (lane == r) my_out_idx = (unsigned)(best & 0xffffffffu);

        if (h == best) {
            k0 = k1; k1 = k2; k2 = k3; k3 = SENT;
            unsigned idx = (unsigned)(best & 0xffffffffu);
            int slot = (int)(idx >> 5);
#pragma unroll
            for (int w = 0; w < 8; w++)
                if (w == (slot >> 5)) mask[w] |= (1u << (slot & 31));

            if (k0 == SENT) {  // rare exact rebuild of remaining top-4
#pragma unroll
                for (int w = 0; w < 8; w++) {
                    unsigned m = mask[w];
                    for (int j = 0; j < 32; j++) {
                        if ((m >> j) & 1u) continue;
                        int pi = ((w << 5) + j) * 32 + lane;
                        float4 p = __ldg(&xp[pi]);
                        float dx = __fsub_rn(cx, p.x);
                        float dy = __fsub_rn(cy, p.y);
                        float dz = __fsub_rn(cz, p.z);
                        float d = __fadd_rn(
                            __fadd_rn(__fmul_rn(dx, dx), __fmul_rn(dy, dy)),
                            __fmul_rn(dz, dz));
                        unsigned long long k =
                            ((unsigned long long)__float_as_uint(d) << 32) |
                            (unsigned)pi;
                        ins4(k, k0, k1, k2, k3);
                    }
                }
            }
        }
        __syncwarp(0xffffffffu);
    }

    float4 p = __ldg(&xp[my_out_idx]);
    float* o = neigh + ((size_t)c * 32 + lane) * 3;
    o[0] = p.x; o[1] = p.y; o[2] = p.z;
}

// ---------------------------------------------------------------------------
// Launch
// ---------------------------------------------------------------------------
extern "C" void kernel_launch(void* const* d_in, const int* in_sizes, int n_in,
                              void* d_out, int out_size) {
    const float* xyz  = (const float*)d_in[0];
    const float* pose = (const float*)d_in[1];
    if (n_in >= 2 && in_sizes[0] == BB * 12) {
        xyz  = (const float*)d_in[1];
        pose = (const float*)d_in[0];
    }
    float* out = (float*)d_out;
    float* neigh  = out;
    float* center = out + (size_t)BB * NG * GS * 3;

    xform_k<<<(BB * NN + 255) / 256, 256>>>(xyz, pose);
    fps_k<<<BB * FPB, 1024>>>(center);
    knn_k<<<(BB * NG) / 8, 256>>>(center, neigh);
}

// round 5
// speedup vs baseline: 3.5436x; 3.5436x over previous
#include <cuda_runtime.h>
#include <cstdint>

#define BB 8
#define NN 8192
#define NG 512
#define GS 32
#define CSZ 8   // fps cluster size (CTAs per batch)

// Scratch: transformed points (float4 for vectorized loads). 1 MB.
__device__ float4 g_x[BB * NN];

__device__ __forceinline__ uint32_t smem_u32(const void* p) {
    return (uint32_t)__cvta_generic_to_shared(p);
}

// ---------------------------------------------------------------------------
// Kernel 1: SE3 transform.  x = R @ p + t
// ---------------------------------------------------------------------------
__global__ void xform_k(const float* __restrict__ xyz,
                        const float* __restrict__ pose) {
    int i = blockIdx.x * blockDim.x + threadIdx.x;
    if (i >= BB * NN) return;
    int b = i >> 13;
    const float* P = pose + b * 12;
    float x = xyz[3 * i + 0];
    float y = xyz[3 * i + 1];
    float z = xyz[3 * i + 2];
    float r0 = __fadd_rn(__fmaf_rn(__ldg(P + 2), z,
               __fmaf_rn(__ldg(P + 1), y, __fmul_rn(__ldg(P + 0), x))), __ldg(P + 3));
    float r1 = __fadd_rn(__fmaf_rn(__ldg(P + 6), z,
               __fmaf_rn(__ldg(P + 5), y, __fmul_rn(__ldg(P + 4), x))), __ldg(P + 7));
    float r2 = __fadd_rn(__fmaf_rn(__ldg(P + 10), z,
               __fmaf_rn(__ldg(P + 9), y, __fmul_rn(__ldg(P + 8), x))), __ldg(P + 11));
    g_x[i] = make_float4(r0, r1, r2, 0.0f);
}

// ---------------------------------------------------------------------------
// Kernel 2: FPS. 8-CTA cluster per batch (1 point/thread).
// Per iteration:
//   redux warp argmax -> 32 leaders atomicMax tagged key into smem -> bar ->
//   tid0 publishes FINAL CTA key to its own DSMEM-visible slot (relaxed,
//   cluster scope) -> warp0 lanes 0..7 poll the 8 remote slots until every
//   tag == g+1 (ballot-converged; warps 1..31 sleep at __syncthreads, issuing
//   nothing) -> butterfly max of 8 -> lane0 STS winner -> bar -> all LDS.
// Key: (g+1)<<45 | dist_bits<<13 | (8191-idx)  -> max == (max dist, min idx)
// Tags are monotone => stale buffer contents always lose; no resets needed.
// One cluster barrier at start guarantees slot init before any remote poll.
// ---------------------------------------------------------------------------
__global__ __launch_bounds__(1024, 1) __cluster_dims__(CSZ, 1, 1)
void fps_k(float* __restrict__ center_out) {
    const int tid = threadIdx.x;
    const int b = blockIdx.x >> 3;   // batch
    const int r = blockIdx.x & 7;    // rank in cluster

    __shared__ unsigned long long s_lkey[2];  // CTA-local argmax accumulator
    __shared__ unsigned long long s_pub[2];   // published key (DSMEM-read by peers)
    __shared__ unsigned long long s_win[2];   // cluster winner broadcast

    if (tid == 0) {
        s_lkey[0] = 0; s_lkey[1] = 0;
        s_pub[0] = 0;  s_pub[1] = 0;
        s_win[0] = 0;  s_win[1] = 0;
    }
    __syncthreads();
    // all CTAs' slot inits visible before anyone polls remotely
    asm volatile("barrier.cluster.arrive.aligned;" ::: "memory");
    asm volatile("barrier.cluster.wait.aligned;" ::: "memory");

    const float4* __restrict__ xp = g_x + b * NN;
    const unsigned pidx = (unsigned)r * 1024u + (unsigned)tid;
    float4 p = __ldg(&xp[pidx]);
    float dst = 1e10f;

    // remote pub-slot addresses (shared::cluster) for ranks 0..7
    const uint32_t pub_a = smem_u32(&s_pub[0]);
    uint32_t pub_own;
    asm("mapa.shared::cluster.u32 %0, %1, %2;"
        : "=r"(pub_own) : "r"(pub_a), "r"((unsigned)r));
    const int lane = tid & 31;
    uint32_t pub_rem = 0;
    if (lane < CSZ)
        asm("mapa.shared::cluster.u32 %0, %1, %2;"
            : "=r"(pub_rem) : "r"(pub_a), "r"((unsigned)lane));

    if (r == 0 && tid == 0) {
        float4 c0 = __ldg(&xp[0]);
        center_out[(b * NG) * 3 + 0] = c0.x;
        center_out[(b * NG) * 3 + 1] = c0.y;
        center_out[(b * NG) * 3 + 2] = c0.z;
    }

    unsigned widx = 0;  // current center index (uniform across cluster)

    for (int g = 0; g < NG - 1; g++) {
        const int buf = g & 1;
        const unsigned tagv = (unsigned)(g + 1);

        // --- distance update vs current center ---
        float4 c = __ldg(&xp[widx]);
        float dx = __fsub_rn(p.x, c.x);
        float dy = __fsub_rn(p.y, c.y);
        float dz = __fsub_rn(p.z, c.z);
        float d = __fadd_rn(__fadd_rn(__fmul_rn(dx, dx), __fmul_rn(dy, dy)),
                            __fmul_rn(dz, dz));
        dst = fminf(dst, d);

        // --- warp argmax via redux (uint order == float order for x >= 0) ---
        unsigned db = __float_as_uint(dst);
        unsigned wmax;
        asm volatile("redux.sync.max.u32 %0, %1, 0xffffffff;"
                     : "=r"(wmax) : "r"(db));
        unsigned cand = (db == wmax) ? pidx : 0xffffffffu;
        unsigned minidx;
        asm volatile("redux.sync.min.u32 %0, %1, 0xffffffff;"
                     : "=r"(minidx) : "r"(cand));

        // --- CTA reduce: 32 leaders atomicMax tagged key ---
        if ((tid & 31) == 0) {
            unsigned long long key = ((unsigned long long)tagv << 45) |
                                     ((unsigned long long)wmax << 13) |
                                     (8191u - minidx);
            atomicMax(&s_lkey[buf], key);
        }
        __syncthreads();  // all leader atomics complete

        // --- tid0 publishes the FINAL CTA key (cluster-visible) ---
        if (tid == 0) {
            unsigned long long k = s_lkey[buf];
            asm volatile("st.relaxed.cluster.shared::cluster.b64 [%0], %1;"
                         :: "r"(pub_own + (unsigned)buf * 8u), "l"(k) : "memory");
        }

        // --- warp 0: poll all 8 remote slots; other warps sleep at barrier ---
        if (tid < 32) {
            unsigned long long v = 0ull;
            bool ok = (lane >= CSZ);
            for (;;) {
                if (!ok) {
                    asm volatile("ld.relaxed.cluster.shared::cluster.b64 %0, [%1];"
                                 : "=l"(v) : "r"(pub_rem + (unsigned)buf * 8u)
                                 : "memory");
                    ok = ((unsigned)(v >> 45) == tagv);
                }
                if (__ballot_sync(0xffffffffu, ok) == 0xffffffffu) break;
            }
            // butterfly max over the 8 values (other lanes hold 0)
#pragma unroll
            for (int o = 16; o > 0; o >>= 1) {
                unsigned long long w = __shfl_xor_sync(0xffffffffu, v, o);
                v = v > w ? v : w;
            }
            if (lane == 0) {
                s_win[buf] = v;
                if (r == 0) {
                    unsigned wi = 8191u - (unsigned)(v & 0x1fffu);
                    float4 cw = __ldg(&xp[wi]);
                    float* o = center_out + (b * NG + g + 1) * 3;
                    o[0] = cw.x; o[1] = cw.y; o[2] = cw.z;
                }
            }
        }
        __syncthreads();
        widx = 8191u - (unsigned)(s_win[buf] & 0x1fffu);
    }
}

// ---------------------------------------------------------------------------
// Kernel 3: exact 32-NN per center (unchanged from passing version).
// ---------------------------------------------------------------------------
__device__ __forceinline__ void ins4(unsigned long long k,
                                     unsigned long long& k0, unsigned long long& k1,
                                     unsigned long long& k2, unsigned long long& k3) {
    if (k < k3) {
        if (k < k2) {
            k3 = k2;
            if (k < k1) {
                k2 = k1;
                if (k < k0) { k1 = k0; k0 = k; } else { k1 = k; }
            } else { k2 = k; }
        } else { k3 = k; }
    }
}

__global__ __launch_bounds__(256) void knn_k(const float* __restrict__ center,
                                             float* __restrict__ neigh) {
    const int warp = threadIdx.x >> 5;
    const int lane = threadIdx.x & 31;
    const int c = blockIdx.x * 8 + warp;
    const int b = c >> 9;

    const float cx = __ldg(center + c * 3 + 0);
    const float cy = __ldg(center + c * 3 + 1);
    const float cz = __ldg(center + c * 3 + 2);
    const float4* xp = g_x + b * NN;

    const unsigned long long SENT = ~0ull;
    unsigned long long k0 = SENT, k1 = SENT, k2 = SENT, k3 = SENT;
    unsigned mask[8] = {0, 0, 0, 0, 0, 0, 0, 0};

    for (int i = 0; i < 256; i++) {
        int idx = i * 32 + lane;
        float4 p = __ldg(&xp[idx]);
        float dx = __fsub_rn(cx, p.x);
        float dy = __fsub_rn(cy, p.y);
        float dz = __fsub_rn(cz, p.z);
        float d = __fadd_rn(__fadd_rn(__fmul_rn(dx, dx), __fmul_rn(dy, dy)),
                            __fmul_rn(dz, dz));
        unsigned long long k =
            ((unsigned long long)__float_as_uint(d) << 32) | (unsigned)idx;
        ins4(k, k0, k1, k2, k3);
    }

    unsigned my_out_idx = 0;
    for (int r = 0; r < 32; r++) {
        unsigned long long h = k0;
        unsigned long long best = h;
#pragma unroll
        for (int o = 16; o > 0; o >>= 1) {
            unsigned long long v = __shfl_xor_sync(0xffffffffu, best, o);
            best = best < v ? best : v;
        }
        if (lane == r) my_out_idx = (unsigned)(best & 0xffffffffu);

        if (h == best) {
            k0 = k1; k1 = k2; k2 = k3; k3 = SENT;
            unsigned idx = (unsigned)(best & 0xffffffffu);
            int slot = (int)(idx >> 5);
#pragma unroll
            for (int w = 0; w < 8; w++)
                if (w == (slot >> 5)) mask[w] |= (1u << (slot & 31));

            if (k0 == SENT) {  // rare exact rebuild of remaining top-4
#pragma unroll
                for (int w = 0; w < 8; w++) {
                    unsigned m = mask[w];
                    for (int j = 0; j < 32; j++) {
                        if ((m >> j) & 1u) continue;
                        int pi = ((w << 5) + j) * 32 + lane;
                        float4 p = __ldg(&xp[pi]);
                        float dx = __fsub_rn(cx, p.x);
                        float dy = __fsub_rn(cy, p.y);
                        float dz = __fsub_rn(cz, p.z);
                        float d = __fadd_rn(
                            __fadd_rn(__fmul_rn(dx, dx), __fmul_rn(dy, dy)),
                            __fmul_rn(dz, dz));
                        unsigned long long k =
                            ((unsigned long long)__float_as_uint(d) << 32) |
                            (unsigned)pi;
                        ins4(k, k0, k1, k2, k3);
                    }
                }
            }
        }
        __syncwarp(0xffffffffu);
    }

    float4 p = __ldg(&xp[my_out_idx]);
    float* o = neigh + ((size_t)c * 32 + lane) * 3;
    o[0] = p.x; o[1] = p.y; o[2] = p.z;
}

// ---------------------------------------------------------------------------
// Launch
// ---------------------------------------------------------------------------
extern "C" void kernel_launch(void* const* d_in, const int* in_sizes, int n_in,
                              void* d_out, int out_size) {
    const float* xyz  = (const float*)d_in[0];
    const float* pose = (const float*)d_in[1];
    if (n_in >= 2 && in_sizes[0] == BB * 12) {
        xyz  = (const float*)d_in[1];
        pose = (const float*)d_in[0];
    }
    float* out = (float*)d_out;
    float* neigh  = out;
    float* center = out + (size_t)BB * NG * GS * 3;

    xform_k<<<(BB * NN + 255) / 256, 256>>>(xyz, pose);
    fps_k<<<BB * CSZ, 1024>>>(center);
    knn_k<<<(BB * NG) / 8, 256>>>(center, neigh);
}

// round 6
// speedup vs baseline: 5.3944x; 1.5223x over previous
#include <cuda_runtime.h>
#include <cstdint>

#define BB 8
#define NN 8192
#define NG 512
#define GS 32

// Scratch: transformed points (float4 for vectorized loads). 1 MB.
__device__ float4 g_x[BB * NN];

// packed f32x2 helpers (per-lane IEEE rn — bit-identical to scalar __fadd_rn/__fmul_rn)
#define MUL2(out, a, b) asm("mul.rn.f32x2 %0, %1, %2;" : "=l"(out) : "l"(a), "l"(b))
#define ADD2(out, a, b) asm("add.rn.f32x2 %0, %1, %2;" : "=l"(out) : "l"(a), "l"(b))
#define PACK2(out, lo, hi) asm("mov.b64 %0, {%1, %2};" : "=l"(out) : "r"(lo), "r"(hi))
#define UNPACK2(lo, hi, in) asm("mov.b64 {%0, %1}, %2;" : "=r"(lo), "=r"(hi) : "l"(in))

// ---------------------------------------------------------------------------
// Kernel 1: SE3 transform.  x = R @ p + t
// ---------------------------------------------------------------------------
__global__ void xform_k(const float* __restrict__ xyz,
                        const float* __restrict__ pose) {
    int i = blockIdx.x * blockDim.x + threadIdx.x;
    if (i >= BB * NN) return;
    int b = i >> 13;
    const float* P = pose + b * 12;
    float x = xyz[3 * i + 0];
    float y = xyz[3 * i + 1];
    float z = xyz[3 * i + 2];
    float r0 = __fadd_rn(__fmaf_rn(__ldg(P + 2), z,
               __fmaf_rn(__ldg(P + 1), y, __fmul_rn(__ldg(P + 0), x))), __ldg(P + 3));
    float r1 = __fadd_rn(__fmaf_rn(__ldg(P + 6), z,
               __fmaf_rn(__ldg(P + 5), y, __fmul_rn(__ldg(P + 4), x))), __ldg(P + 7));
    float r2 = __fadd_rn(__fmaf_rn(__ldg(P + 10), z,
               __fmaf_rn(__ldg(P + 9), y, __fmul_rn(__ldg(P + 8), x))), __ldg(P + 11));
    g_x[i] = make_float4(r0, r1, r2, 0.0f);
}

// no-op spacer so ncu's fixed skip-count lands on fps_k / knn_k
__global__ void nop_k() {}

// ---------------------------------------------------------------------------
// Kernel 2: FPS. One CTA (1024 thr) per batch; 8 pts/thread in registers
// (packed f32x2). Per iteration — ONE barrier, NO atomics:
//   packed dist update + scalar fminf -> 7-FMNMX max tree ->
//   redux.sync.max(dist bits) + rare equality scan + redux.sync.min(idx) ->
//   warp leader STS (dist,idx) into double-buffered per-warp slots -> bar ->
//   EVERY warp redundantly reduces the 32 slots (2 LDS + 2 redux), giving
//   all threads the winner index with no second barrier.
// Double buffering makes next-iter STS safe vs. laggard readers; the barrier
// at iter g+1 prevents any warp getting 2 iterations ahead.
// Tie-breaks: argmax -> first (min) index, matching jnp.argmax.
// ---------------------------------------------------------------------------
__global__ __launch_bounds__(1024, 1) void fps_k(float* __restrict__ center_out) {
    const int b = blockIdx.x;
    const int tid = threadIdx.x;
    const int wid = tid >> 5;
    const int lane = tid & 31;

    __shared__ unsigned s_d[2][32];
    __shared__ unsigned s_i[2][32];

    const float4* __restrict__ xp = g_x + b * NN;

    // load 8 points/thread, pack into f32x2 pairs (slots 2j, 2j+1)
    unsigned long long px2[4], py2[4], pz2[4];
    float dst[8];
    {
        float px[8], py[8], pz[8];
#pragma unroll
        for (int s = 0; s < 8; s++) {
            float4 p = xp[s * 1024 + tid];
            px[s] = p.x; py[s] = p.y; pz[s] = p.z;
            dst[s] = 1e10f;
        }
#pragma unroll
        for (int j = 0; j < 4; j++) {
            PACK2(px2[j], __float_as_uint(px[2 * j]), __float_as_uint(px[2 * j + 1]));
            PACK2(py2[j], __float_as_uint(py[2 * j]), __float_as_uint(py[2 * j + 1]));
            PACK2(pz2[j], __float_as_uint(pz[2 * j]), __float_as_uint(pz[2 * j + 1]));
        }
    }

    if (tid == 0) {
        float4 c0 = __ldg(&xp[0]);
        center_out[(b * NG) * 3 + 0] = c0.x;
        center_out[(b * NG) * 3 + 1] = c0.y;
        center_out[(b * NG) * 3 + 2] = c0.z;
    }

    unsigned widx = 0;  // current center index (uniform)

    for (int g = 0; g < NG - 1; g++) {
        const int buf = g & 1;

        // --- uniform center load (L1-resident) + packed negation ---
        float4 c = __ldg(&xp[widx]);
        unsigned long long ncx, ncy, ncz;
        {
            unsigned nx = __float_as_uint(-c.x);
            unsigned ny = __float_as_uint(-c.y);
            unsigned nz = __float_as_uint(-c.z);
            PACK2(ncx, nx, nx);
            PACK2(ncy, ny, ny);
            PACK2(ncz, nz, nz);
        }

        // --- packed distance update (bit-identical to scalar rn ops) ---
#pragma unroll
        for (int j = 0; j < 4; j++) {
            unsigned long long dx, dy, dz, xx, yy, zz, ss, dd;
            ADD2(dx, px2[j], ncx);           // p - c (add of negation: exact)
            ADD2(dy, py2[j], ncy);
            ADD2(dz, pz2[j], ncz);
            MUL2(xx, dx, dx);
            MUL2(yy, dy, dy);
            ADD2(ss, xx, yy);                // dx*dx + dy*dy
            MUL2(zz, dz, dz);
            ADD2(dd, ss, zz);                // (dx*dx+dy*dy) + dz*dz
            unsigned d0u, d1u;
            UNPACK2(d0u, d1u, dd);
            dst[2 * j]     = fminf(dst[2 * j],     __uint_as_float(d0u));
            dst[2 * j + 1] = fminf(dst[2 * j + 1], __uint_as_float(d1u));
        }

        // --- per-thread max via FMNMX tree (no FSETP chain) ---
        float m01 = fmaxf(dst[0], dst[1]);
        float m23 = fmaxf(dst[2], dst[3]);
        float m45 = fmaxf(dst[4], dst[5]);
        float m67 = fmaxf(dst[6], dst[7]);
        float m03 = fmaxf(m01, m23);
        float m47 = fmaxf(m45, m67);
        float dmax = fmaxf(m03, m47);

        // --- warp argmax: redux over bits (uint order == float order, x>=0) ---
        unsigned db = __float_as_uint(dmax);
        unsigned wmax;
        asm volatile("redux.sync.max.u32 %0, %1, 0xffffffff;"
                     : "=r"(wmax) : "r"(db));
        unsigned cand = 0xffffffffu;
        if (db == wmax) {  // rare: ~1 lane per warp
#pragma unroll
            for (int s = 7; s >= 0; s--)
                if (__float_as_uint(dst[s]) == wmax)
                    cand = (unsigned)(s * 1024 + tid);  // descending s -> min idx kept
        }
        unsigned wi;
        asm volatile("redux.sync.min.u32 %0, %1, 0xffffffff;"
                     : "=r"(wi) : "r"(cand));

        // --- leader publishes; ONE barrier; replicated cross-warp reduce ---
        if (lane == 0) { s_d[buf][wid] = wmax; s_i[buf][wid] = wi; }
        __syncthreads();

        unsigned d2 = s_d[buf][lane];
        unsigned i2 = s_i[buf][lane];
        unsigned gmax;
        asm volatile("redux.sync.max.u32 %0, %1, 0xffffffff;"
                     : "=r"(gmax) : "r"(d2));
        unsigned cand2 = (d2 == gmax) ? i2 : 0xffffffffu;
        asm volatile("redux.sync.min.u32 %0, %1, 0xffffffff;"
                     : "=r"(widx) : "r"(cand2));

        if (tid == 0) {
            float4 cw = __ldg(&xp[widx]);
            float* o = center_out + (b * NG + g + 1) * 3;
            o[0] = cw.x; o[1] = cw.y; o[2] = cw.z;
        }
    }
}

// ---------------------------------------------------------------------------
// Kernel 3: exact 32-NN per center (unchanged from passing version).
// ---------------------------------------------------------------------------
__device__ __forceinline__ void ins4(unsigned long long k,
                                     unsigned long long& k0, unsigned long long& k1,
                                     unsigned long long& k2, unsigned long long& k3) {
    if (k < k3) {
        if (k < k2) {
            k3 = k2;
            if (k < k1) {
                k2 = k1;
                if (k < k0) { k1 = k0; k0 = k; } else { k1 = k; }
            } else { k2 = k; }
        } else { k3 = k; }
    }
}

__global__ __launch_bounds__(256) void knn_k(const float* __restrict__ center,
                                             float* __restrict__ neigh) {
    const int warp = threadIdx.x >> 5;
    const int lane = threadIdx.x & 31;
    const int c = blockIdx.x * 8 + warp;
    const int b = c >> 9;

    const float cx = __ldg(center + c * 3 + 0);
    const float cy = __ldg(center + c * 3 + 1);
    const float cz = __ldg(center + c * 3 + 2);
    const float4* xp = g_x + b * NN;

    const unsigned long long SENT = ~0ull;
    unsigned long long k0 = SENT, k1 = SENT, k2 = SENT, k3 = SENT;
    unsigned mask[8] = {0, 0, 0, 0, 0, 0, 0, 0};

    for (int i = 0; i < 256; i++) {
        int idx = i * 32 + lane;
        float4 p = __ldg(&xp[idx]);
        float dx = __fsub_rn(cx, p.x);
        float dy = __fsub_rn(cy, p.y);
        float dz = __fsub_rn(cz, p.z);
        float d = __fadd_rn(__fadd_rn(__fmul_rn(dx, dx), __fmul_rn(dy, dy)),
                            __fmul_rn(dz, dz));
        unsigned long long k =
            ((unsigned long long)__float_as_uint(d) << 32) | (unsigned)idx;
        ins4(k, k0, k1, k2, k3);
    }

    unsigned my_out_idx = 0;
    for (int r = 0; r < 32; r++) {
        unsigned long long h = k0;
        unsigned long long best = h;
#pragma unroll
        for (int o = 16; o > 0; o >>= 1) {
            unsigned long long v = __shfl_xor_sync(0xffffffffu, best, o);
            best = best < v ? best : v;
        }
        if (lane == r) my_out_idx = (unsigned)(best & 0xffffffffu);

        if (h == best) {
            k0 = k1; k1 = k2; k2 = k3; k3 = SENT;
            unsigned idx = (unsigned)(best & 0xffffffffu);
            int slot = (int)(idx >> 5);
#pragma unroll
            for (int w = 0; w < 8; w++)
                if (w == (slot >> 5)) mask[w] |= (1u << (slot & 31));

            if (k0 == SENT) {  // rare exact rebuild of remaining top-4
#pragma unroll
                for (int w = 0; w < 8; w++) {
                    unsigned m = mask[w];
                    for (int j = 0; j < 32; j++) {
                        if ((m >> j) & 1u) continue;
                        int pi = ((w << 5) + j) * 32 + lane;
                        float4 p = __ldg(&xp[pi]);
                        float dx = __fsub_rn(cx, p.x);
                        float dy = __fsub_rn(cy, p.y);
                        float dz = __fsub_rn(cz, p.z);
                        float d = __fadd_rn(
                            __fadd_rn(__fmul_rn(dx, dx), __fmul_rn(dy, dy)),
                            __fmul_rn(dz, dz));
                        unsigned long long k =
                            ((unsigned long long)__float_as_uint(d) << 32) |
                            (unsigned)pi;
                        ins4(k, k0, k1, k2, k3);
                    }
                }
            }
        }
        __syncwarp(0xffffffffu);
    }

    float4 p = __ldg(&xp[my_out_idx]);
    float* o = neigh + ((size_t)c * 32 + lane) * 3;
    o[0] = p.x; o[1] = p.y; o[2] = p.z;
}

// ---------------------------------------------------------------------------
// Launch
// ---------------------------------------------------------------------------
extern "C" void kernel_launch(void* const* d_in, const int* in_sizes, int n_in,
                              void* d_out, int out_size) {
    const float* xyz  = (const float*)d_in[0];
    const float* pose = (const float*)d_in[1];
    if (n_in >= 2 && in_sizes[0] == BB * 12) {
        xyz  = (const float*)d_in[1];
        pose = (const float*)d_in[0];
    }
    float* out = (float*)d_out;
    float* neigh  = out;
    float* center = out + (size_t)BB * NG * GS * 3;

    xform_k<<<(BB * NN + 255) / 256, 256>>>(xyz, pose);
    nop_k<<<1, 32>>>();   // spacer: shifts ncu's fixed capture slot onto fps/knn
    fps_k<<<BB, 1024>>>(center);
    knn_k<<<(BB * NG) / 8, 256>>>(center, neigh);
}

// round 7
// speedup vs baseline: 6.2221x; 1.1534x over previous
#include <cuda_runtime.h>
#include <cstdint>

#define BB 8
#define NN 8192
#define NG 512
#define GS 32

// Scratch: transformed points (float4 for vectorized loads). 1 MB.
__device__ float4 g_x[BB * NN];

// packed f32x2 helpers (per-lane IEEE rn — bit-identical to scalar __fadd_rn/__fmul_rn)
#define MUL2(out, a, b) asm("mul.rn.f32x2 %0, %1, %2;" : "=l"(out) : "l"(a), "l"(b))
#define ADD2(out, a, b) asm("add.rn.f32x2 %0, %1, %2;" : "=l"(out) : "l"(a), "l"(b))
#define PACK2(out, lo, hi) asm("mov.b64 %0, {%1, %2};" : "=l"(out) : "r"(lo), "r"(hi))
#define UNPACK2(lo, hi, in) asm("mov.b64 {%0, %1}, %2;" : "=r"(lo), "=r"(hi) : "l"(in))

// ---------------------------------------------------------------------------
// Kernel 1: SE3 transform.  x = R @ p + t
// ---------------------------------------------------------------------------
__global__ void xform_k(const float* __restrict__ xyz,
                        const float* __restrict__ pose) {
    int i = blockIdx.x * blockDim.x + threadIdx.x;
    if (i >= BB * NN) return;
    int b = i >> 13;
    const float* P = pose + b * 12;
    float x = xyz[3 * i + 0];
    float y = xyz[3 * i + 1];
    float z = xyz[3 * i + 2];
    float r0 = __fadd_rn(__fmaf_rn(__ldg(P + 2), z,
               __fmaf_rn(__ldg(P + 1), y, __fmul_rn(__ldg(P + 0), x))), __ldg(P + 3));
    float r1 = __fadd_rn(__fmaf_rn(__ldg(P + 6), z,
               __fmaf_rn(__ldg(P + 5), y, __fmul_rn(__ldg(P + 4), x))), __ldg(P + 7));
    float r2 = __fadd_rn(__fmaf_rn(__ldg(P + 10), z,
               __fmaf_rn(__ldg(P + 9), y, __fmul_rn(__ldg(P + 8), x))), __ldg(P + 11));
    g_x[i] = make_float4(r0, r1, r2, 0.0f);
}

// no-op spacer (keeps ncu's fixed capture slot off xform_k)
__global__ void nop_k() {}

// ---------------------------------------------------------------------------
// Kernel 2: FPS (unchanged from the passing 499us version).
// ---------------------------------------------------------------------------
__global__ __launch_bounds__(1024, 1) void fps_k(float* __restrict__ center_out) {
    const int b = blockIdx.x;
    const int tid = threadIdx.x;
    const int wid = tid >> 5;
    const int lane = tid & 31;

    __shared__ unsigned s_d[2][32];
    __shared__ unsigned s_i[2][32];

    const float4* __restrict__ xp = g_x + b * NN;

    unsigned long long px2[4], py2[4], pz2[4];
    float dst[8];
    {
        float px[8], py[8], pz[8];
#pragma unroll
        for (int s = 0; s < 8; s++) {
            float4 p = xp[s * 1024 + tid];
            px[s] = p.x; py[s] = p.y; pz[s] = p.z;
            dst[s] = 1e10f;
        }
#pragma unroll
        for (int j = 0; j < 4; j++) {
            PACK2(px2[j], __float_as_uint(px[2 * j]), __float_as_uint(px[2 * j + 1]));
            PACK2(py2[j], __float_as_uint(py[2 * j]), __float_as_uint(py[2 * j + 1]));
            PACK2(pz2[j], __float_as_uint(pz[2 * j]), __float_as_uint(pz[2 * j + 1]));
        }
    }

    if (tid == 0) {
        float4 c0 = __ldg(&xp[0]);
        center_out[(b * NG) * 3 + 0] = c0.x;
        center_out[(b * NG) * 3 + 1] = c0.y;
        center_out[(b * NG) * 3 + 2] = c0.z;
    }

    unsigned widx = 0;

    for (int g = 0; g < NG - 1; g++) {
        const int buf = g & 1;

        float4 c = __ldg(&xp[widx]);
        unsigned long long ncx, ncy, ncz;
        {
            unsigned nx = __float_as_uint(-c.x);
            unsigned ny = __float_as_uint(-c.y);
            unsigned nz = __float_as_uint(-c.z);
            PACK2(ncx, nx, nx);
            PACK2(ncy, ny, ny);
            PACK2(ncz, nz, nz);
        }

#pragma unroll
        for (int j = 0; j < 4; j++) {
            unsigned long long dx, dy, dz, xx, yy, zz, ss, dd;
            ADD2(dx, px2[j], ncx);
            ADD2(dy, py2[j], ncy);
            ADD2(dz, pz2[j], ncz);
            MUL2(xx, dx, dx);
            MUL2(yy, dy, dy);
            ADD2(ss, xx, yy);
            MUL2(zz, dz, dz);
            ADD2(dd, ss, zz);
            unsigned d0u, d1u;
            UNPACK2(d0u, d1u, dd);
            dst[2 * j]     = fminf(dst[2 * j],     __uint_as_float(d0u));
            dst[2 * j + 1] = fminf(dst[2 * j + 1], __uint_as_float(d1u));
        }

        float m01 = fmaxf(dst[0], dst[1]);
        float m23 = fmaxf(dst[2], dst[3]);
        float m45 = fmaxf(dst[4], dst[5]);
        float m67 = fmaxf(dst[6], dst[7]);
        float m03 = fmaxf(m01, m23);
        float m47 = fmaxf(m45, m67);
        float dmax = fmaxf(m03, m47);

        unsigned db = __float_as_uint(dmax);
        unsigned wmax;
        asm volatile("redux.sync.max.u32 %0, %1, 0xffffffff;"
                     : "=r"(wmax) : "r"(db));
        unsigned cand = 0xffffffffu;
        if (db == wmax) {
#pragma unroll
            for (int s = 7; s >= 0; s--)
                if (__float_as_uint(dst[s]) == wmax)
                    cand = (unsigned)(s * 1024 + tid);
        }
        unsigned wi;
        asm volatile("redux.sync.min.u32 %0, %1, 0xffffffff;"
                     : "=r"(wi) : "r"(cand));

        if (lane == 0) { s_d[buf][wid] = wmax; s_i[buf][wid] = wi; }
        __syncthreads();

        unsigned d2 = s_d[buf][lane];
        unsigned i2 = s_i[buf][lane];
        unsigned gmax;
        asm volatile("redux.sync.max.u32 %0, %1, 0xffffffff;"
                     : "=r"(gmax) : "r"(d2));
        unsigned cand2 = (d2 == gmax) ? i2 : 0xffffffffu;
        asm volatile("redux.sync.min.u32 %0, %1, 0xffffffff;"
                     : "=r"(widx) : "r"(cand2));

        if (tid == 0) {
            float4 cw = __ldg(&xp[widx]);
            float* o = center_out + (b * NG + g + 1) * 3;
            o[0] = cw.x; o[1] = cw.y; o[2] = cw.z;
        }
    }
}

// ---------------------------------------------------------------------------
// Kernel 3: exact 32-NN, v2.
//   - per-lane sorted top-6 (sentinel (+inf,~0)); float threshold gate so the
//     common path per point is 1 FSETP (exact: scan idx monotone -> d==thr
//     correctly loses the (dist,idx) tie)
//   - scan unrolled x4 with up-front loads (MLP=4)
//   - extraction: 2x redux.sync per round (min dist-bits, min idx among ties)
//   - exact rescan fallback if a lane's 6-buffer empties (P ~ 1e-4 per lane)
// ---------------------------------------------------------------------------
#define SK 0x7f800000FFFFFFFFULL  // (+inf, idx ~0): bigger than any real key

__device__ __forceinline__ void ins6(unsigned long long key,
                                     unsigned long long& k0, unsigned long long& k1,
                                     unsigned long long& k2, unsigned long long& k3,
                                     unsigned long long& k4, unsigned long long& k5) {
    // caller guarantees key < k5
    if (key < k4) {
        k5 = k4;
        if (key < k3) {
            k4 = k3;
            if (key < k2) {
                k3 = k2;
                if (key < k1) {
                    k2 = k1;
                    if (key < k0) { k1 = k0; k0 = key; } else { k1 = key; }
                } else { k2 = key; }
            } else { k3 = key; }
        } else { k4 = key; }
    } else { k5 = key; }
}

__device__ __forceinline__ float distc(float cx, float cy, float cz, float4 p) {
    float dx = __fsub_rn(cx, p.x);
    float dy = __fsub_rn(cy, p.y);
    float dz = __fsub_rn(cz, p.z);
    return __fadd_rn(__fadd_rn(__fmul_rn(dx, dx), __fmul_rn(dy, dy)),
                     __fmul_rn(dz, dz));
}

__global__ __launch_bounds__(256) void knn_k(const float* __restrict__ center,
                                             float* __restrict__ neigh) {
    const int warp = threadIdx.x >> 5;
    const int lane = threadIdx.x & 31;
    const int c = blockIdx.x * 8 + warp;
    const int b = c >> 9;

    const float cx = __ldg(center + c * 3 + 0);
    const float cy = __ldg(center + c * 3 + 1);
    const float cz = __ldg(center + c * 3 + 2);
    const float4* xp = g_x + b * NN;

    unsigned long long k0 = SK, k1 = SK, k2 = SK, k3 = SK, k4 = SK, k5 = SK;
    float thr = __int_as_float(0x7f800000);  // +inf
    unsigned mask[8] = {0, 0, 0, 0, 0, 0, 0, 0};

#pragma unroll 1
    for (int i = 0; i < 256; i += 4) {
        float4 p0 = __ldg(&xp[(i + 0) * 32 + lane]);
        float4 p1 = __ldg(&xp[(i + 1) * 32 + lane]);
        float4 p2 = __ldg(&xp[(i + 2) * 32 + lane]);
        float4 p3 = __ldg(&xp[(i + 3) * 32 + lane]);
        float d0 = distc(cx, cy, cz, p0);
        float d1 = distc(cx, cy, cz, p1);
        float d2 = distc(cx, cy, cz, p2);
        float d3 = distc(cx, cy, cz, p3);
        if (d0 < thr) {
            unsigned long long key = ((unsigned long long)__float_as_uint(d0) << 32)
                                     | (unsigned)((i + 0) * 32 + lane);
            ins6(key, k0, k1, k2, k3, k4, k5);
            thr = __uint_as_float((unsigned)(k5 >> 32));
        }
        if (d1 < thr) {
            unsigned long long key = ((unsigned long long)__float_as_uint(d1) << 32)
                                     | (unsigned)((i + 1) * 32 + lane);
            ins6(key, k0, k1, k2, k3, k4, k5);
            thr = __uint_as_float((unsigned)(k5 >> 32));
        }
        if (d2 < thr) {
            unsigned long long key = ((unsigned long long)__float_as_uint(d2) << 32)
                                     | (unsigned)((i + 2) * 32 + lane);
            ins6(key, k0, k1, k2, k3, k4, k5);
            thr = __uint_as_float((unsigned)(k5 >> 32));
        }
        if (d3 < thr) {
            unsigned long long key = ((unsigned long long)__float_as_uint(d3) << 32)
                                     | (unsigned)((i + 3) * 32 + lane);
            ins6(key, k0, k1, k2, k3, k4, k5);
            thr = __uint_as_float((unsigned)(k5 >> 32));
        }
    }

    unsigned my_out_idx = 0;
    for (int r = 0; r < 32; r++) {
        unsigned dhi = (unsigned)(k0 >> 32);
        unsigned gmin;
        asm volatile("redux.sync.min.u32 %0, %1, 0xffffffff;"
                     : "=r"(gmin) : "r"(dhi));
        unsigned cand = (dhi == gmin) ? (unsigned)(k0 & 0xffffffffu) : 0xffffffffu;
        unsigned widx;
        asm volatile("redux.sync.min.u32 %0, %1, 0xffffffff;"
                     : "=r"(widx) : "r"(cand));
        if (lane == r) my_out_idx = widx;

        if (cand == widx) {  // unique winner lane (lane point sets disjoint)
            k0 = k1; k1 = k2; k2 = k3; k3 = k4; k4 = k5; k5 = SK;
            int slot = (int)(widx >> 5);  // which of my 256 points
#pragma unroll
            for (int w = 0; w < 8; w++)
                if (w == (slot >> 5)) mask[w] |= (1u << (slot & 31));

            if (k0 == SK) {  // rare: exact rebuild of remaining top-6
                thr = __int_as_float(0x7f800000);
#pragma unroll
                for (int w = 0; w < 8; w++) {
                    unsigned m = mask[w];
                    for (int j = 0; j < 32; j++) {
                        if ((m >> j) & 1u) continue;
                        int pi = ((w << 5) + j) * 32 + lane;
                        float4 p = __ldg(&xp[pi]);
                        float d = distc(cx, cy, cz, p);
                        if (d < thr) {
                            unsigned long long key =
                                ((unsigned long long)__float_as_uint(d) << 32) |
                                (unsigned)pi;
                            ins6(key, k0, k1, k2, k3, k4, k5);
                            thr = __uint_as_float((unsigned)(k5 >> 32));
                        }
                    }
                }
            }
        }
    }

    float4 p = __ldg(&xp[my_out_idx]);
    float* o = neigh + ((size_t)c * 32 + lane) * 3;
    o[0] = p.x; o[1] = p.y; o[2] = p.z;
}

// ---------------------------------------------------------------------------
// Launch
// ---------------------------------------------------------------------------
extern "C" void kernel_launch(void* const* d_in, const int* in_sizes, int n_in,
                              void* d_out, int out_size) {
    const float* xyz  = (const float*)d_in[0];
    const float* pose = (const float*)d_in[1];
    if (n_in >= 2 && in_sizes[0] == BB * 12) {
        xyz  = (const float*)d_in[1];
        pose = (const float*)d_in[0];
    }
    float* out = (float*)d_out;
    float* neigh  = out;
    float* center = out + (size_t)BB * NG * GS * 3;

    xform_k<<<(BB * NN + 255) / 256, 256>>>(xyz, pose);
    nop_k<<<1, 32>>>();
    fps_k<<<BB, 1024>>>(center);
    knn_k<<<(BB * NG) / 8, 256>>>(center, neigh);
}